// round 1
// baseline (speedup 1.0000x reference)
#include <cuda_runtime.h>
#include <math.h>

#define S 128
#define B 32
#define H 1024
#define E 1024
#define V 32000
#define SB (S*B)        /* 4096  */
#define BH (B*H)        /* 32768 */

// ---------------- scratch (device globals; no allocations allowed) ----------
__device__ float g_embeds[SB*H];   // embeds for layer1, reused as l2_out
__device__ float g_xi[SB*H];       // xi for current layer
__device__ float g_xf[SB*H];       // xf for current layer
__device__ float g_l1[SB*H];       // layer-1 outputs (x for layer 2)
__device__ float g_latA[BH];
__device__ float g_latB[BH];
__device__ float g_part[2*16*B*H]; // partial gate preacts [gate][kc][b][h]
__device__ float g_WhiT[H*H];
__device__ float g_WhfT[H*H];
__device__ float g_Whi2T[H*H];
__device__ float g_Whf2T[H*H];

// ---------------- embedding gather ------------------------------------------
__global__ void k_embed(const int* __restrict__ word, const float* __restrict__ emb)
{
    int row = blockIdx.x;                     // s*B + b
    int w = word[row];
    const float4* src = reinterpret_cast<const float4*>(emb + (size_t)w * E);
    float4* dst = reinterpret_cast<float4*>(g_embeds + (size_t)row * E);
    dst[threadIdx.x] = src[threadIdx.x];      // 256 threads * float4 = 1024
}

// ---------------- 1024x1024 transpose (for recurrent weights) ---------------
__global__ void k_transpose(const float* __restrict__ W, float* __restrict__ WT)
{
    __shared__ float tile[32][33];
    int kx = blockIdx.x * 32 + threadIdx.x;   // k (col of W)
    int h0 = blockIdx.y * 32;                 // h (row of W)
    #pragma unroll
    for (int j = threadIdx.y; j < 32; j += 8)
        tile[j][threadIdx.x] = W[(size_t)(h0 + j) * H + kx];
    __syncthreads();
    int ho = blockIdx.y * 32 + threadIdx.x;   // h out col
    int k0 = blockIdx.x * 32;                 // k out row
    #pragma unroll
    for (int j = threadIdx.y; j < 32; j += 8)
        WT[(size_t)(k0 + j) * H + ho] = tile[threadIdx.x][j];
}

// ---------------- recurrence: gate partial GEMM ------------------------------
// grid (16 hblk, 16 kchunk, 2 gates), 256 threads.
// partial[gate][kc][b][h] = sum_{k in chunk} lat[b,k] * W[h,k]
__global__ void __launch_bounds__(256) k_r1(int parity, int layer)
{
    const float* lat = parity ? g_latB : g_latA;
    const float* WT;
    if (layer == 0) WT = blockIdx.z ? g_WhfT  : g_WhiT;
    else            WT = blockIdx.z ? g_Whf2T : g_Whi2T;
    int h0 = blockIdx.x * 64;
    int k0 = blockIdx.y * 64;

    __shared__ float sLat[32][68];   // padded, float4-aligned rows
    __shared__ float sW[64][64];     // [k][h]

    int tid = threadIdx.x;
    #pragma unroll
    for (int i = tid; i < 512; i += 256) {               // 32b x 64k
        int b = i >> 4, k4 = i & 15;
        float4 v = *reinterpret_cast<const float4*>(lat + b * H + k0 + k4 * 4);
        *reinterpret_cast<float4*>(&sLat[b][k4 * 4]) = v;
    }
    #pragma unroll
    for (int i = tid; i < 1024; i += 256) {              // 64k x 64h
        int k = i >> 4, h4 = i & 15;
        float4 v = *reinterpret_cast<const float4*>(WT + (size_t)(k0 + k) * H + h0 + h4 * 4);
        *reinterpret_cast<float4*>(&sW[k][h4 * 4]) = v;
    }
    __syncthreads();

    int hh = tid & 63, bq = tid >> 6;   // thread: 1 h, 8 batches (bq*8..bq*8+7)
    float acc[8] = {0,0,0,0,0,0,0,0};
    #pragma unroll
    for (int k = 0; k < 64; k += 4) {
        float w0 = sW[k][hh], w1 = sW[k+1][hh], w2 = sW[k+2][hh], w3 = sW[k+3][hh];
        #pragma unroll
        for (int j = 0; j < 8; j++) {
            float4 l = *reinterpret_cast<const float4*>(&sLat[bq*8 + j][k]);
            acc[j] += l.x*w0 + l.y*w1 + l.z*w2 + l.w*w3;
        }
    }
    float* p = g_part + ((size_t)(blockIdx.z * 16 + blockIdx.y) * 32) * H + h0 + hh;
    #pragma unroll
    for (int j = 0; j < 8; j++) p[(size_t)(bq*8 + j) * H] = acc[j];
}

// ---------------- recurrence: reduce + sigmoid + state update ----------------
__global__ void k_r2(int parity, int t, int layer,
                     float* __restrict__ out_ig, float* __restrict__ out_fg)
{
    int idx = blockIdx.x * 256 + threadIdx.x;   // 0..32767 = b*H + h
    int b = idx >> 10, h = idx & 1023;
    const float* latO = parity ? g_latB : g_latA;
    float* latN       = parity ? g_latA : g_latB;

    float si = 0.f, sf = 0.f;
    #pragma unroll
    for (int kc = 0; kc < 16; kc++) {
        si += g_part[((size_t)kc * 32 + b) * H + h];
        sf += g_part[((size_t)(16 + kc) * 32 + b) * H + h];
    }
    size_t o = (size_t)t * BH + idx;
    float pi = si + g_xi[o];
    float pf = sf + g_xf[o];
    float ig = 1.f / (1.f + expf(-pi));
    float fg = 1.f / (1.f + expf(-pf));
    const float* x = layer ? g_l1 : g_embeds;
    float* lout    = layer ? g_embeds : g_l1;
    float ln = ig * x[o] + fg * latO[idx];
    latN[idx] = ln;
    lout[o]   = ln;
    if (out_ig) { out_ig[idx] = ig; out_fg[idx] = fg; }
}

// ---------------- generic NT GEMM: C[M,N] = A[M,K] * Bm[N,K]^T + bias --------
// 128x128 tile, BK=16, 256 threads, 8x8 microtile (4+4 split to avoid LDS conflicts)
__global__ void __launch_bounds__(256) k_gemm(
    const float* __restrict__ A, const float* __restrict__ Bm,
    const float* __restrict__ bias, float* __restrict__ C,
    int M, int N, int K)
{
    __shared__ float sA[16][128];
    __shared__ float sB[16][128];
    int tid = threadIdx.x;
    int tx = tid & 15, ty = tid >> 4;
    int m0 = blockIdx.y * 128, n0 = blockIdx.x * 128;
    int lr = tid >> 2;        // 0..63
    int lc = (tid & 3) * 4;   // 0,4,8,12

    float c[8][8];
    #pragma unroll
    for (int i = 0; i < 8; i++)
        #pragma unroll
        for (int j = 0; j < 8; j++) c[i][j] = 0.f;

    for (int k0 = 0; k0 < K; k0 += 16) {
        #pragma unroll
        for (int i = 0; i < 2; i++) {
            int r = lr + i * 64;
            float4 va = *reinterpret_cast<const float4*>(A  + (size_t)(m0 + r) * K + k0 + lc);
            sA[lc+0][r] = va.x; sA[lc+1][r] = va.y; sA[lc+2][r] = va.z; sA[lc+3][r] = va.w;
            float4 vb = *reinterpret_cast<const float4*>(Bm + (size_t)(n0 + r) * K + k0 + lc);
            sB[lc+0][r] = vb.x; sB[lc+1][r] = vb.y; sB[lc+2][r] = vb.z; sB[lc+3][r] = vb.w;
        }
        __syncthreads();
        #pragma unroll
        for (int kk = 0; kk < 16; kk++) {
            float4 a0 = *reinterpret_cast<const float4*>(&sA[kk][ty*4]);
            float4 a1 = *reinterpret_cast<const float4*>(&sA[kk][64 + ty*4]);
            float4 b0 = *reinterpret_cast<const float4*>(&sB[kk][tx*4]);
            float4 b1 = *reinterpret_cast<const float4*>(&sB[kk][64 + tx*4]);
            float av[8] = {a0.x,a0.y,a0.z,a0.w,a1.x,a1.y,a1.z,a1.w};
            float bv[8] = {b0.x,b0.y,b0.z,b0.w,b1.x,b1.y,b1.z,b1.w};
            #pragma unroll
            for (int i = 0; i < 8; i++)
                #pragma unroll
                for (int j = 0; j < 8; j++)
                    c[i][j] += av[i] * bv[j];
        }
        __syncthreads();
    }

    float bl[4] = {0,0,0,0}, bh_[4] = {0,0,0,0};
    if (bias) {
        float4 t0 = *reinterpret_cast<const float4*>(bias + n0 + tx*4);
        float4 t1 = *reinterpret_cast<const float4*>(bias + n0 + 64 + tx*4);
        bl[0]=t0.x; bl[1]=t0.y; bl[2]=t0.z; bl[3]=t0.w;
        bh_[0]=t1.x; bh_[1]=t1.y; bh_[2]=t1.z; bh_[3]=t1.w;
    }
    #pragma unroll
    for (int i = 0; i < 8; i++) {
        int m = m0 + ((i < 4) ? (ty*4 + i) : (64 + ty*4 + (i - 4)));
        float4 v0, v1;
        v0.x = c[i][0] + bl[0]; v0.y = c[i][1] + bl[1];
        v0.z = c[i][2] + bl[2]; v0.w = c[i][3] + bl[3];
        v1.x = c[i][4] + bh_[0]; v1.y = c[i][5] + bh_[1];
        v1.z = c[i][6] + bh_[2]; v1.w = c[i][7] + bh_[3];
        *reinterpret_cast<float4*>(C + (size_t)m * N + n0 + tx*4)      = v0;
        *reinterpret_cast<float4*>(C + (size_t)m * N + n0 + 64 + tx*4) = v1;
    }
}

// -----------------------------------------------------------------------------
extern "C" void kernel_launch(void* const* d_in, const int* in_sizes, int n_in,
                              void* d_out, int out_size)
{
    (void)in_sizes; (void)n_in; (void)out_size;
    const int*   word   = (const int*)  d_in[0];
    const float* latent = (const float*)d_in[1];
    const float* emb    = (const float*)d_in[2];
    const float* h2o_w  = (const float*)d_in[3];
    const float* h2o_b  = (const float*)d_in[4];
    const float* Whi    = (const float*)d_in[5];
    const float* Wxi_w  = (const float*)d_in[6];
    const float* Wxi_b  = (const float*)d_in[7];
    const float* Whf    = (const float*)d_in[8];
    const float* Wxf_w  = (const float*)d_in[9];
    const float* Wxf_b  = (const float*)d_in[10];
    const float* Whi2   = (const float*)d_in[11];
    const float* Wxi2_w = (const float*)d_in[12];
    const float* Wxi2_b = (const float*)d_in[13];
    const float* Whf2   = (const float*)d_in[14];
    const float* Wxf2_w = (const float*)d_in[15];
    const float* Wxf2_b = (const float*)d_in[16];
    float* out = (float*)d_out;

    float *p_embeds, *p_xi, *p_xf, *p_l1, *p_latA;
    float *p_WhiT, *p_WhfT, *p_Whi2T, *p_Whf2T;
    cudaGetSymbolAddress((void**)&p_embeds, g_embeds);
    cudaGetSymbolAddress((void**)&p_xi,     g_xi);
    cudaGetSymbolAddress((void**)&p_xf,     g_xf);
    cudaGetSymbolAddress((void**)&p_l1,     g_l1);
    cudaGetSymbolAddress((void**)&p_latA,   g_latA);
    cudaGetSymbolAddress((void**)&p_WhiT,   g_WhiT);
    cudaGetSymbolAddress((void**)&p_WhfT,   g_WhfT);
    cudaGetSymbolAddress((void**)&p_Whi2T,  g_Whi2T);
    cudaGetSymbolAddress((void**)&p_Whf2T,  g_Whf2T);

    const size_t OUT_LOG = BH;
    const size_t OUT_IG  = BH + (size_t)SB * V;
    const size_t OUT_FG  = OUT_IG + BH;

    dim3 tgrid(32, 32), tblk(32, 8);
    k_transpose<<<tgrid, tblk>>>(Whi,  p_WhiT);
    k_transpose<<<tgrid, tblk>>>(Whf,  p_WhfT);
    k_transpose<<<tgrid, tblk>>>(Whi2, p_Whi2T);
    k_transpose<<<tgrid, tblk>>>(Whf2, p_Whf2T);

    k_embed<<<SB, 256>>>(word, emb);

    // layer-1 input gate preactivations (batched over all steps)
    dim3 ggrid(H/128, SB/128);
    k_gemm<<<ggrid, 256>>>(p_embeds, Wxi_w, Wxi_b, p_xi, SB, H, E);
    k_gemm<<<ggrid, 256>>>(p_embeds, Wxf_w, Wxf_b, p_xf, SB, H, E);

    cudaMemcpyAsync(p_latA, latent, (size_t)BH * sizeof(float),
                    cudaMemcpyDeviceToDevice);

    dim3 rgrid(16, 16, 2);
    for (int t = 0; t < S; t++) {
        int parity = t & 1;
        k_r1<<<rgrid, 256>>>(parity, 0);
        k_r2<<<BH/256, 256>>>(parity, t, 0, nullptr, nullptr);
    }

    // layer-2 input gate preactivations from l1 outputs
    k_gemm<<<ggrid, 256>>>(p_l1, Wxi2_w, Wxi2_b, p_xi, SB, H, H);
    k_gemm<<<ggrid, 256>>>(p_l1, Wxf2_w, Wxf2_b, p_xf, SB, H, H);

    for (int t = 0; t < S; t++) {
        int parity = t & 1;
        k_r1<<<rgrid, 256>>>(parity, 1);
        float* oig = (t == S-1) ? out + OUT_IG : nullptr;
        float* ofg = (t == S-1) ? out + OUT_FG : nullptr;
        k_r2<<<BH/256, 256>>>(parity, t, 1, oig, ofg);
    }

    // logits: [4096,1024] x [32000,1024]^T + bias
    dim3 lgrid(V/128, SB/128);
    k_gemm<<<lgrid, 256>>>(p_embeds /* = l2_out */, h2o_w, h2o_b,
                           out + OUT_LOG, SB, V, H);

    // final latent
    cudaMemcpyAsync(out, p_latA, (size_t)BH * sizeof(float),
                    cudaMemcpyDeviceToDevice);
}

// round 3
// speedup vs baseline: 1.5530x; 1.5530x over previous
#include <cuda_runtime.h>
#include <cuda_bf16.h>
#include <math.h>
#include <stdint.h>

#define S 128
#define B 32
#define H 1024
#define E 1024
#define V 32000
#define SB (S*B)        /* 4096  */
#define BH (B*H)        /* 32768 */

// ---------------- scratch (device globals; no allocations allowed) ----------
__device__ float g_embeds[SB*H];   // embeds for layer1, reused as l2_out
__device__ float g_xi[SB*H];
__device__ float g_xf[SB*H];
__device__ float g_l1[SB*H];
__device__ float g_latA[BH];
__device__ float g_latB[BH];
__device__ float g_part[2*16*B*H];
__device__ float g_WhiT[H*H];
__device__ float g_WhfT[H*H];
__device__ float g_Whi2T[H*H];
__device__ float g_Whf2T[H*H];
// bf16 split operands for tensor-core GEMMs
__device__ __nv_bfloat16 g_Ah[SB*H];
__device__ __nv_bfloat16 g_Al[SB*H];
__device__ __nv_bfloat16 g_Bh[(size_t)V*H];
__device__ __nv_bfloat16 g_Bl[(size_t)V*H];

// ============================ helpers ========================================
__device__ __forceinline__ uint32_t smem_u32(const void* p) {
    uint32_t a;
    asm("{ .reg .u64 t; cvta.to.shared.u64 t, %1; cvt.u32.u64 %0, t; }"
        : "=r"(a) : "l"(p));
    return a;
}
__device__ __forceinline__ void cpa16(uint32_t s, const void* g) {
    asm volatile("cp.async.cg.shared.global [%0], [%1], 16;" :: "r"(s), "l"(g) : "memory");
}
#define LDSM_X4(r0,r1,r2,r3,addr) \
    asm volatile("ldmatrix.sync.aligned.m8n8.x4.shared.b16 {%0,%1,%2,%3}, [%4];" \
        : "=r"(r0),"=r"(r1),"=r"(r2),"=r"(r3) : "r"(addr))
#define MMA_BF16(c, a, b0, b1) \
    asm volatile("mma.sync.aligned.m16n8k16.row.col.f32.bf16.bf16.f32 " \
        "{%0,%1,%2,%3}, {%4,%5,%6,%7}, {%8,%9}, {%0,%1,%2,%3};" \
        : "+f"((c)[0]),"+f"((c)[1]),"+f"((c)[2]),"+f"((c)[3]) \
        : "r"((a)[0]),"r"((a)[1]),"r"((a)[2]),"r"((a)[3]), "r"(b0),"r"(b1))

// ================= split-bf16 HMMA GEMM ======================================
// C[M,Nld](fp32) = Ah*Bh^T + Al*Bh^T + Ah*Bl^T + bias
// block tile 128x128, BK=32, 256 threads (warps 2M x 4N, warp tile 64x32).
// smem rows padded to 80B -> conflict-free ldmatrix, no swizzle.
#define ROWP 40                      /* bf16 elems per smem row (80B) */
#define MAT_B (128*ROWP*2)           /* 10240 bytes per matrix tile   */
#define STG_B (4*MAT_B)              /* 40960 bytes per stage         */
#define GEMM_SMEM (2*STG_B)          /* 81920                         */

__global__ void __launch_bounds__(256, 1)
k_hmma(const __nv_bfloat16* __restrict__ Ah, const __nv_bfloat16* __restrict__ Al,
       const __nv_bfloat16* __restrict__ Bh, const __nv_bfloat16* __restrict__ Bl,
       const float* __restrict__ bias, float* __restrict__ C,
       int Kdim, int Nld)
{
    extern __shared__ __align__(16) char dsmem[];
    uint32_t sbase = smem_u32(dsmem);

    const int tid  = threadIdx.x;
    const int lane = tid & 31;
    const int warp = tid >> 5;
    const int wm   = warp & 1;    // 0..1  -> rows wm*64
    const int wn   = warp >> 1;   // 0..3  -> cols wn*32
    const int m0   = blockIdx.x * 128;
    const int n0   = blockIdx.y * 128;

    float c[4][4][4];
    #pragma unroll
    for (int i = 0; i < 4; i++)
        #pragma unroll
        for (int j = 0; j < 4; j++)
            #pragma unroll
            for (int q = 0; q < 4; q++) c[i][j][q] = 0.f;

    const int NS = Kdim >> 5;   // K / 32

    // stage loader: 4 matrices x 128 rows x 32 bf16 (4x16B chunks per row)
    auto load_stage = [&](int s, int buf) {
        int k0 = s * 32;
        uint32_t sb = sbase + buf * STG_B;
        #pragma unroll
        for (int it = 0; it < 8; it++) {
            int idx = tid + it * 256;          // 0..2047
            int mat = idx >> 9;                // 0 Ah, 1 Al, 2 Bh, 3 Bl
            int rem = idx & 511;
            int row = rem >> 2;
            int ch  = rem & 3;
            const __nv_bfloat16* g;
            if (mat == 0)      g = Ah + (size_t)(m0 + row) * Kdim;
            else if (mat == 1) g = Al + (size_t)(m0 + row) * Kdim;
            else if (mat == 2) g = Bh + (size_t)(n0 + row) * Kdim;
            else               g = Bl + (size_t)(n0 + row) * Kdim;
            cpa16(sb + mat * MAT_B + row * 80 + ch * 16, g + k0 + ch * 8);
        }
        asm volatile("cp.async.commit_group;" ::: "memory");
    };

    load_stage(0, 0);

    for (int s = 0; s < NS; s++) {
        int buf = s & 1;
        if (s + 1 < NS) {
            load_stage(s + 1, (s + 1) & 1);
            asm volatile("cp.async.wait_group 1;" ::: "memory");
        } else {
            asm volatile("cp.async.wait_group 0;" ::: "memory");
        }
        __syncthreads();

        uint32_t sb = sbase + buf * STG_B;
        #pragma unroll
        for (int ks = 0; ks < 2; ks++) {
            // B fragments: 2 x ldmatrix.x4 per matrix (covers n32 k16)
            uint32_t bh[2][4], bl[2][4];
            {
                int brow = wn * 32 + ((lane >> 4) << 3) + (lane & 7);
                int bk   = ks * 16 + ((lane >> 3) & 1) * 8;
                #pragma unroll
                for (int p = 0; p < 2; p++) {
                    uint32_t ab = sb + 2 * MAT_B + (brow + p * 16) * 80 + bk * 2;
                    LDSM_X4(bh[p][0], bh[p][1], bh[p][2], bh[p][3], ab);
                    LDSM_X4(bl[p][0], bl[p][1], bl[p][2], bl[p][3], ab + MAT_B);
                }
            }
            int arow = wm * 64 + (lane & 15);
            int ak   = ks * 16 + (lane >> 4) * 8;
            #pragma unroll
            for (int mt = 0; mt < 4; mt++) {
                uint32_t aa = sb + (arow + mt * 16) * 80 + ak * 2;
                uint32_t ah[4], al[4];
                LDSM_X4(ah[0], ah[1], ah[2], ah[3], aa);
                LDSM_X4(al[0], al[1], al[2], al[3], aa + MAT_B);
                #pragma unroll
                for (int p = 0; p < 2; p++) {
                    #pragma unroll
                    for (int hf = 0; hf < 2; hf++) {
                        int nt = p * 2 + hf;
                        uint32_t b0h = bh[p][hf*2], b1h = bh[p][hf*2+1];
                        uint32_t b0l = bl[p][hf*2], b1l = bl[p][hf*2+1];
                        MMA_BF16(c[mt][nt], ah, b0h, b1h);
                        MMA_BF16(c[mt][nt], al, b0h, b1h);
                        MMA_BF16(c[mt][nt], ah, b0l, b1l);
                    }
                }
            }
        }
        __syncthreads();
    }

    // epilogue
    const int mw = m0 + wm * 64;
    const int nw = n0 + wn * 32;
    #pragma unroll
    for (int mt = 0; mt < 4; mt++) {
        int r = mw + mt * 16 + (lane >> 2);
        #pragma unroll
        for (int nt = 0; nt < 4; nt++) {
            int cc = nw + nt * 8 + (lane & 3) * 2;
            float bx = bias[cc], by = bias[cc + 1];
            float2 v0 = { c[mt][nt][0] + bx, c[mt][nt][1] + by };
            float2 v1 = { c[mt][nt][2] + bx, c[mt][nt][3] + by };
            *reinterpret_cast<float2*>(C + (size_t)r * Nld + cc)       = v0;
            *reinterpret_cast<float2*>(C + (size_t)(r + 8) * Nld + cc) = v1;
        }
    }
}

// ---------------- fp32 -> bf16 hi/lo split -----------------------------------
__global__ void k_split(const float* __restrict__ x,
                        __nv_bfloat16* __restrict__ hi,
                        __nv_bfloat16* __restrict__ lo, int n4)
{
    int i = blockIdx.x * 256 + threadIdx.x;
    if (i >= n4) return;
    float4 v = reinterpret_cast<const float4*>(x)[i];
    __nv_bfloat16 h0 = __float2bfloat16(v.x);
    __nv_bfloat16 h1 = __float2bfloat16(v.y);
    __nv_bfloat16 h2 = __float2bfloat16(v.z);
    __nv_bfloat16 h3 = __float2bfloat16(v.w);
    __nv_bfloat16 l0 = __float2bfloat16(v.x - __bfloat162float(h0));
    __nv_bfloat16 l1 = __float2bfloat16(v.y - __bfloat162float(h1));
    __nv_bfloat16 l2 = __float2bfloat16(v.z - __bfloat162float(h2));
    __nv_bfloat16 l3 = __float2bfloat16(v.w - __bfloat162float(h3));
    __nv_bfloat162 hp0 = {h0, h1}, hp1 = {h2, h3};
    __nv_bfloat162 lp0 = {l0, l1}, lp1 = {l2, l3};
    reinterpret_cast<__nv_bfloat162*>(hi)[i * 2 + 0] = hp0;
    reinterpret_cast<__nv_bfloat162*>(hi)[i * 2 + 1] = hp1;
    reinterpret_cast<__nv_bfloat162*>(lo)[i * 2 + 0] = lp0;
    reinterpret_cast<__nv_bfloat162*>(lo)[i * 2 + 1] = lp1;
}

// ---------------- embedding gather -------------------------------------------
__global__ void k_embed(const int* __restrict__ word, const float* __restrict__ emb)
{
    int row = blockIdx.x;
    int w = word[row];
    const float4* src = reinterpret_cast<const float4*>(emb + (size_t)w * E);
    float4* dst = reinterpret_cast<float4*>(g_embeds + (size_t)row * E);
    dst[threadIdx.x] = src[threadIdx.x];
}

// ---------------- 1024x1024 transpose ----------------------------------------
__global__ void k_transpose(const float* __restrict__ W, float* __restrict__ WT)
{
    __shared__ float tile[32][33];
    int kx = blockIdx.x * 32 + threadIdx.x;
    int h0 = blockIdx.y * 32;
    #pragma unroll
    for (int j = threadIdx.y; j < 32; j += 8)
        tile[j][threadIdx.x] = W[(size_t)(h0 + j) * H + kx];
    __syncthreads();
    int ho = blockIdx.y * 32 + threadIdx.x;
    int k0 = blockIdx.x * 32;
    #pragma unroll
    for (int j = threadIdx.y; j < 32; j += 8)
        WT[(size_t)(k0 + j) * H + ho] = tile[threadIdx.x][j];
}

// ---------------- recurrence: gate partial GEMM -------------------------------
__global__ void __launch_bounds__(256) k_r1(int parity, int layer)
{
    const float* lat = parity ? g_latB : g_latA;
    const float* WT;
    if (layer == 0) WT = blockIdx.z ? g_WhfT  : g_WhiT;
    else            WT = blockIdx.z ? g_Whf2T : g_Whi2T;
    int h0 = blockIdx.x * 64;
    int k0 = blockIdx.y * 64;

    __shared__ float sLat[32][68];
    __shared__ float sW[64][64];

    int tid = threadIdx.x;
    #pragma unroll
    for (int i = tid; i < 512; i += 256) {
        int b = i >> 4, k4 = i & 15;
        float4 v = *reinterpret_cast<const float4*>(lat + b * H + k0 + k4 * 4);
        *reinterpret_cast<float4*>(&sLat[b][k4 * 4]) = v;
    }
    #pragma unroll
    for (int i = tid; i < 1024; i += 256) {
        int k = i >> 4, h4 = i & 15;
        float4 v = *reinterpret_cast<const float4*>(WT + (size_t)(k0 + k) * H + h0 + h4 * 4);
        *reinterpret_cast<float4*>(&sW[k][h4 * 4]) = v;
    }
    __syncthreads();

    int hh = tid & 63, bq = tid >> 6;
    float acc[8] = {0,0,0,0,0,0,0,0};
    #pragma unroll
    for (int k = 0; k < 64; k += 4) {
        float w0 = sW[k][hh], w1 = sW[k+1][hh], w2 = sW[k+2][hh], w3 = sW[k+3][hh];
        #pragma unroll
        for (int j = 0; j < 8; j++) {
            float4 l = *reinterpret_cast<const float4*>(&sLat[bq*8 + j][k]);
            acc[j] += l.x*w0 + l.y*w1 + l.z*w2 + l.w*w3;
        }
    }
    float* p = g_part + ((size_t)(blockIdx.z * 16 + blockIdx.y) * 32) * H + h0 + hh;
    #pragma unroll
    for (int j = 0; j < 8; j++) p[(size_t)(bq*8 + j) * H] = acc[j];
}

// ---------------- recurrence: reduce + sigmoid + update -----------------------
__global__ void k_r2(int parity, int t, int layer,
                     float* __restrict__ out_ig, float* __restrict__ out_fg)
{
    int idx = blockIdx.x * 256 + threadIdx.x;
    int b = idx >> 10;
    const float* latO = parity ? g_latB : g_latA;
    float* latN       = parity ? g_latA : g_latB;

    float si = 0.f, sf = 0.f;
    #pragma unroll
    for (int kc = 0; kc < 16; kc++) {
        si += g_part[((size_t)kc * 32 + b) * H + (idx & 1023)];
        sf += g_part[((size_t)(16 + kc) * 32 + b) * H + (idx & 1023)];
    }
    size_t o = (size_t)t * BH + idx;
    float pi = si + g_xi[o];
    float pf = sf + g_xf[o];
    float ig = 1.f / (1.f + expf(-pi));
    float fg = 1.f / (1.f + expf(-pf));
    const float* x = layer ? g_l1 : g_embeds;
    float* lout    = layer ? g_embeds : g_l1;
    float ln = ig * x[o] + fg * latO[idx];
    latN[idx] = ln;
    lout[o]   = ln;
    if (out_ig) { out_ig[idx] = ig; out_fg[idx] = fg; }
}

// -----------------------------------------------------------------------------
extern "C" void kernel_launch(void* const* d_in, const int* in_sizes, int n_in,
                              void* d_out, int out_size)
{
    (void)in_sizes; (void)n_in; (void)out_size;
    const int*   word   = (const int*)  d_in[0];
    const float* latent = (const float*)d_in[1];
    const float* emb    = (const float*)d_in[2];
    const float* h2o_w  = (const float*)d_in[3];
    const float* h2o_b  = (const float*)d_in[4];
    const float* Whi    = (const float*)d_in[5];
    const float* Wxi_w  = (const float*)d_in[6];
    const float* Wxi_b  = (const float*)d_in[7];
    const float* Whf    = (const float*)d_in[8];
    const float* Wxf_w  = (const float*)d_in[9];
    const float* Wxf_b  = (const float*)d_in[10];
    const float* Whi2   = (const float*)d_in[11];
    const float* Wxi2_w = (const float*)d_in[12];
    const float* Wxi2_b = (const float*)d_in[13];
    const float* Whf2   = (const float*)d_in[14];
    const float* Wxf2_w = (const float*)d_in[15];
    const float* Wxf2_b = (const float*)d_in[16];
    float* out = (float*)d_out;

    float *p_embeds, *p_xi, *p_xf, *p_l1, *p_latA;
    float *p_WhiT, *p_WhfT, *p_Whi2T, *p_Whf2T;
    __nv_bfloat16 *p_Ah, *p_Al, *p_Bh, *p_Bl;
    cudaGetSymbolAddress((void**)&p_embeds, g_embeds);
    cudaGetSymbolAddress((void**)&p_xi,     g_xi);
    cudaGetSymbolAddress((void**)&p_xf,     g_xf);
    cudaGetSymbolAddress((void**)&p_l1,     g_l1);
    cudaGetSymbolAddress((void**)&p_latA,   g_latA);
    cudaGetSymbolAddress((void**)&p_WhiT,   g_WhiT);
    cudaGetSymbolAddress((void**)&p_WhfT,   g_WhfT);
    cudaGetSymbolAddress((void**)&p_Whi2T,  g_Whi2T);
    cudaGetSymbolAddress((void**)&p_Whf2T,  g_Whf2T);
    cudaGetSymbolAddress((void**)&p_Ah,     g_Ah);
    cudaGetSymbolAddress((void**)&p_Al,     g_Al);
    cudaGetSymbolAddress((void**)&p_Bh,     g_Bh);
    cudaGetSymbolAddress((void**)&p_Bl,     g_Bl);

    cudaFuncSetAttribute(k_hmma, cudaFuncAttributeMaxDynamicSharedMemorySize,
                         GEMM_SMEM);

    const size_t OUT_LOG = BH;
    const size_t OUT_IG  = BH + (size_t)SB * V;
    const size_t OUT_FG  = OUT_IG + BH;

    dim3 tgrid(32, 32), tblk(32, 8);
    k_transpose<<<tgrid, tblk>>>(Whi,  p_WhiT);
    k_transpose<<<tgrid, tblk>>>(Whf,  p_WhfT);
    k_transpose<<<tgrid, tblk>>>(Whi2, p_Whi2T);
    k_transpose<<<tgrid, tblk>>>(Whf2, p_Whf2T);

    k_embed<<<SB, 256>>>(word, emb);

    const int ACT4 = SB * H / 4;   // 1048576
    const int W4   = H * H / 4;    // 262144
    const int HO4  = V * H / 4;    // 8192000

    // layer-1 input gate preactivations via tensor cores
    k_split<<<ACT4/256, 256>>>(p_embeds, p_Ah, p_Al, ACT4);
    dim3 ggrid(SB/128, H/128);     // (32, 8)
    k_split<<<W4/256, 256>>>(Wxi_w, p_Bh, p_Bl, W4);
    k_hmma<<<ggrid, 256, GEMM_SMEM>>>(p_Ah, p_Al, p_Bh, p_Bl, Wxi_b, p_xi, H, H);
    k_split<<<W4/256, 256>>>(Wxf_w, p_Bh, p_Bl, W4);
    k_hmma<<<ggrid, 256, GEMM_SMEM>>>(p_Ah, p_Al, p_Bh, p_Bl, Wxf_b, p_xf, H, H);

    cudaMemcpyAsync(p_latA, latent, (size_t)BH * sizeof(float),
                    cudaMemcpyDeviceToDevice);

    dim3 rgrid(16, 16, 2);
    for (int t = 0; t < S; t++) {
        int parity = t & 1;
        k_r1<<<rgrid, 256>>>(parity, 0);
        k_r2<<<BH/256, 256>>>(parity, t, 0, nullptr, nullptr);
    }

    // layer-2 input gate preactivations
    k_split<<<ACT4/256, 256>>>(p_l1, p_Ah, p_Al, ACT4);
    k_split<<<W4/256, 256>>>(Wxi2_w, p_Bh, p_Bl, W4);
    k_hmma<<<ggrid, 256, GEMM_SMEM>>>(p_Ah, p_Al, p_Bh, p_Bl, Wxi2_b, p_xi, H, H);
    k_split<<<W4/256, 256>>>(Wxf2_w, p_Bh, p_Bl, W4);
    k_hmma<<<ggrid, 256, GEMM_SMEM>>>(p_Ah, p_Al, p_Bh, p_Bl, Wxf2_b, p_xf, H, H);

    for (int t = 0; t < S; t++) {
        int parity = t & 1;
        k_r1<<<rgrid, 256>>>(parity, 1);
        float* oig = (t == S-1) ? out + OUT_IG : nullptr;
        float* ofg = (t == S-1) ? out + OUT_FG : nullptr;
        k_r2<<<BH/256, 256>>>(parity, t, 1, oig, ofg);
    }

    // logits: [4096,1024] x [32000,1024]^T + bias via tensor cores
    k_split<<<ACT4/256, 256>>>(p_embeds /* = l2_out */, p_Ah, p_Al, ACT4);
    k_split<<<HO4/256, 256>>>(h2o_w, p_Bh, p_Bl, HO4);
    dim3 lgrid(SB/128, V/128);     // (32, 250)
    k_hmma<<<lgrid, 256, GEMM_SMEM>>>(p_Ah, p_Al, p_Bh, p_Bl, h2o_b,
                                      out + OUT_LOG, H, V);

    cudaMemcpyAsync(out, p_latA, (size_t)BH * sizeof(float),
                    cudaMemcpyDeviceToDevice);
}